// round 17
// baseline (speedup 1.0000x reference)
#include <cuda_runtime.h>
#include <math.h>

// Problem constants
#define B      16
#define C      3
#define H      256
#define W      256
#define HW     65536
#define D      196608
#define NEXP   4
#define TOPK   2
#define HID    64
#define FC     6
#define GSLICE 4

// ---------------- packed f32x2 helpers (sm_100+) --------------------------
typedef unsigned long long u64;

__device__ __forceinline__ u64 pack2(float lo, float hi) {
    u64 r;
    asm("mov.b64 %0, {%1, %2};" : "=l"(r) : "f"(lo), "f"(hi));
    return r;
}
__device__ __forceinline__ void unpack2(u64 v, float& lo, float& hi) {
    asm("mov.b64 {%0, %1}, %2;" : "=f"(lo), "=f"(hi) : "l"(v));
}
__device__ __forceinline__ void fma2(u64& d, u64 a, u64 b) {
    asm("fma.rn.f32x2 %0, %1, %2, %0;" : "+l"(d) : "l"(a), "l"(b));
}

// ---------------- device scratch ------------------------------------------
__device__ float g_refsum[B * C];
__device__ float g_part[B * GSLICE * 8];
__device__ float g_gate[B * 2];
__device__ int   g_eidx[B * 2];

// ---------------- K1: sum ref over spatial per (b,c) ----------------------
__global__ void k_refsum(const float* __restrict__ ref) {
    const float4* p = (const float4*)(ref + (size_t)blockIdx.x * HW);
    float s = 0.f;
    for (int i = threadIdx.x; i < HW / 4; i += 256) {
        float4 v = p[i];
        s += (v.x + v.y) + (v.z + v.w);
    }
    __shared__ float sm[256];
    sm[threadIdx.x] = s;
    __syncthreads();
    for (int st = 128; st > 0; st >>= 1) {
        if (threadIdx.x < st) sm[threadIdx.x] += sm[threadIdx.x + st];
        __syncthreads();
    }
    if (threadIdx.x == 0) g_refsum[blockIdx.x] = sm[0];
}

// ---------------- prompt math (FFT chain collapsed to DC bin) -------------
__device__ void prompt_scales(int b,
                              const float* __restrict__ mod_w1,
                              const float* __restrict__ mod_b1,
                              const float* __restrict__ mod_w2,
                              const float* __restrict__ mod_b2,
                              const float* __restrict__ enh_w,
                              const float* __restrict__ enh_b,
                              const float* __restrict__ fre_prompt,
                              float* sc) {
    float s[3];
#pragma unroll
    for (int c = 0; c < 3; c++) s[c] = g_refsum[b * 3 + c] * (1.f / 256.f);
    float p[12];
#pragma unroll
    for (int i = 0; i < 12; i++) {
        int ci = (i < 6) ? i : i - 6;
        p[i] = (ci < 3) ? s[ci] : 0.f;
    }
    float m1[6];
#pragma unroll
    for (int o = 0; o < 6; o++) {
        float a = mod_b1[o];
#pragma unroll
        for (int i = 0; i < 12; i++) a += mod_w1[o * 12 + i] * p[i];
        m1[o] = fmaxf(a, 0.f);
    }
    float m2[6];
#pragma unroll
    for (int o = 0; o < 6; o++) {
        float a = mod_b2[o];
#pragma unroll
        for (int i = 0; i < 6; i++) a += mod_w2[o * 6 + i] * m1[i];
        m2[o] = a;
    }
    float ein[6];
#pragma unroll
    for (int c = 0; c < 6; c++) ein[c] = m2[c] * fre_prompt[c * (H * (W / 2 + 1))];
    float enh[6];
#pragma unroll
    for (int o = 0; o < 6; o++) {
        float a = enh_b[o];
#pragma unroll
        for (int i = 0; i < 6; i++) a += enh_w[o * 6 + i] * ein[i];
        enh[o] = fmaxf(a, 0.f);
    }
    float v0 = enh[0] * (1.f / 256.f);
    float v1 = enh[1] * (1.f / 256.f);
    float v2 = enh[2] * (1.f / 256.f);
    float mx = fmaxf(v0, fmaxf(v1, v2));
    float e0 = expf(v0 - mx), e1 = expf(v1 - mx), e2 = expf(v2 - mx);
    float inv = 1.f / (e0 + e1 + e2);
    sc[0] = 1.f + e0 * inv;
    sc[1] = 1.f + e1 * inv;
    sc[2] = 1.f + e2 * inv;
}

// ---------------- K2: gating matvecs, grid (B, GSLICE) --------------------
__global__ void k_gate_dots(const float* __restrict__ x,
                            const float* __restrict__ w_gate,
                            const float* __restrict__ w_noise,
                            const float* __restrict__ mod_w1,
                            const float* __restrict__ mod_b1,
                            const float* __restrict__ mod_w2,
                            const float* __restrict__ mod_b2,
                            const float* __restrict__ enh_w,
                            const float* __restrict__ enh_b,
                            const float* __restrict__ fre_prompt) {
    const int b = blockIdx.x, sl = blockIdx.y;
    const int tid = threadIdx.x;
    __shared__ float s_sc[3];
    if (tid == 0) {
        float sc[3];
        prompt_scales(b, mod_w1, mod_b1, mod_w2, mod_b2, enh_w, enh_b,
                      fre_prompt, sc);
        s_sc[0] = sc[0]; s_sc[1] = sc[1]; s_sc[2] = sc[2];
    }
    __syncthreads();
    const float sc0 = s_sc[0], sc1 = s_sc[1], sc2 = s_sc[2];
    const float* xb = x + (size_t)b * D;
    float a[8] = {0, 0, 0, 0, 0, 0, 0, 0};
    const float4* wg4 = (const float4*)w_gate;
    const float4* wn4 = (const float4*)w_noise;
    const int i0 = sl * (D / GSLICE), i1 = i0 + D / GSLICE;
    for (int i = i0 + tid; i < i1; i += 512) {
        float sc = (i < HW) ? sc0 : ((i < 2 * HW) ? sc1 : sc2);
        float xv = xb[i] * sc;
        float4 wg = wg4[i];
        float4 wn = wn4[i];
        a[0] += xv * wg.x; a[1] += xv * wg.y; a[2] += xv * wg.z; a[3] += xv * wg.w;
        a[4] += xv * wn.x; a[5] += xv * wn.y; a[6] += xv * wn.z; a[7] += xv * wn.w;
    }
    __shared__ float sm[512 * 8];
#pragma unroll
    for (int k = 0; k < 8; k++) sm[tid * 8 + k] = a[k];
    __syncthreads();
    for (int st = 256; st > 0; st >>= 1) {
        if (tid < st) {
#pragma unroll
            for (int k = 0; k < 8; k++) sm[tid * 8 + k] += sm[(tid + st) * 8 + k];
        }
        __syncthreads();
    }
    if (tid == 0) {
#pragma unroll
        for (int k = 0; k < 8; k++)
            g_part[(b * GSLICE + sl) * 8 + k] = sm[k];
    }
}

// ---------------- K3: noisy top-k gating + load-balance loss --------------
__device__ __forceinline__ float cv2_4(float a, float b, float c, float d) {
    float m = (a + b + c + d) * 0.25f;
    float va = a - m, vb = b - m, vc = c - m, vd = d - m;
    float var = (va * va + vb * vb + vc * vc + vd * vd) * (1.f / 3.f);
    return var / (m * m + 1e-10f);
}

__global__ void k_finalize(const float* __restrict__ noise,
                           float* __restrict__ out, int out_size) {
    const int lane = threadIdx.x;
    float prob[4] = {0, 0, 0, 0};
    float gates[4] = {0, 0, 0, 0};
    if (lane < B) {
        const int b = lane;
        float lg[8];
#pragma unroll
        for (int k = 0; k < 8; k++) {
            float s = 0.f;
#pragma unroll
            for (int sl = 0; sl < GSLICE; sl++)
                s += g_part[(b * GSLICE + sl) * 8 + k];
            lg[k] = s;
        }
        float clean[4], stdv[4], noisy[4];
#pragma unroll
        for (int e = 0; e < 4; e++) {
            clean[e] = lg[e];
            float z = lg[4 + e];
            float sp = (z > 0.f) ? (z + log1pf(expf(-z))) : log1pf(expf(z));
            stdv[e] = sp + 0.01f;
            noisy[e] = clean[e] + noise[b * 4 + e] * stdv[e];
        }
        float v[4] = {noisy[0], noisy[1], noisy[2], noisy[3]};
        int idx[4] = {0, 1, 2, 3};
#pragma unroll
        for (int s = 0; s < 3; s++) {
            int m = s;
#pragma unroll
            for (int j = s + 1; j < 4; j++)
                if (v[j] > v[m]) m = j;
            float tv = v[s]; v[s] = v[m]; v[m] = tv;
            int ti = idx[s]; idx[s] = idx[m]; idx[m] = ti;
        }
        float t1 = v[1], t2 = v[2];
        float mx = fmaxf(v[0], v[1]);
        float e0 = expf(v[0] - mx), e1 = expf(v[1] - mx);
        float inv = 1.f / (e0 + e1);
        float gA = e0 * inv, gB = e1 * inv;
        gates[idx[0]] = gA;
        gates[idx[1]] = gB;
        g_eidx[b * 2 + 0] = idx[0];
        g_eidx[b * 2 + 1] = idx[1];
        g_gate[b * 2 + 0] = gA;
        g_gate[b * 2 + 1] = gB;
#pragma unroll
        for (int e = 0; e < 4; e++) {
            float thr = (noisy[e] > t2) ? t2 : t1;
            float z = (clean[e] - thr) / stdv[e];
            prob[e] = 0.5f * erfcf(-z * 0.70710678118654752f);
        }
    }
#pragma unroll
    for (int off = 16; off > 0; off >>= 1) {
#pragma unroll
        for (int e = 0; e < 4; e++) {
            prob[e]  += __shfl_down_sync(0xffffffffu, prob[e], off);
            gates[e] += __shfl_down_sync(0xffffffffu, gates[e], off);
        }
    }
    if (lane == 0) {
        float loss = (cv2_4(gates[0], gates[1], gates[2], gates[3]) +
                      cv2_4(prob[0], prob[1], prob[2], prob[3])) * 0.01f;
        if (out_size > B * HW) out[B * HW] = loss;
    }
}

// ---------------- K4: fused sparse expert convs (packed f32x2) ------------
// 288 threads, 3 blocks/SM. Chunk = 32 channels = 16 channel-PAIRS.
// conv1 task = (pair-QUAD q, half, row): 8x2x18 = 288 tasks, each thread
// computes TWO channel-pairs (4 channels) over a 9-wide half-row sharing
// one x sliding window -> x-LDS per output nearly halves vs the R16
// one-pair scheme (the dominant wavefront term). ic loop stays unroll-1
// (162 fma2 per trip, same compile-safe body size as the passing R16).
// conv2 reads packed h pairs with LDS.64, folds lanes into persistent
// scalar acc2[16] each iteration. 'part' overlays hs2 at the end.
#define TDIM 16
#define NTHR 288
#define CHP  32
#define XW   21          // xs row stride (floats, odd)
#define HP2  343         // hs2 per-pair block stride in u64 (18*19+1 skew)
#define PICL 274

__global__ void __launch_bounds__(NTHR, 3)
k_expert(const float* __restrict__ x,
         const float* __restrict__ ew1, const float* __restrict__ eb1,
         const float* __restrict__ ew2, const float* __restrict__ eb2,
         float* __restrict__ out) {
    const int b = blockIdx.z, tY = blockIdx.y, tX = blockIdx.x;
    const int tid = threadIdx.x;

    __shared__ float xs[3 * 20 * XW];     // 20160 B
    __shared__ u64   hs2[16 * HP2];       // 43904 B (reused as 'part')
    __shared__ u64   w1p[16 * 27];        // 3456 B  (packed ch-pairs)
    __shared__ u64   w2p[16 * 9];         // 1152 B  (packed, gate-scaled)
    __shared__ float b1s[CHP];

    // load x tile (+halo 2), shared by both experts
    const int gy0 = tY * TDIM - 2, gx0 = tX * TDIM - 2;
    for (int i = tid; i < 3 * 20 * 20; i += NTHR) {
        int c = i / 400, r = (i / 20) % 20, col = i % 20;
        int gy = gy0 + r, gx = gx0 + col;
        float v = 0.f;
        if ((unsigned)gy < 256u && (unsigned)gx < 256u)
            v = x[((size_t)(b * 3 + c) << 16) + (gy << 8) + gx];
        xs[(c * 20 + r) * XW + col] = v;
    }

    const bool interior = (tY > 0) && (tY < H / TDIM - 1) &&
                          (tX > 0) && (tX < W / TDIM - 1);

    // conv1 task: (pair-quad, half, row). 8*2*18 = 288.
    const int c1_q    = tid / 36;            // 0..7 -> pairs {2q, 2q+1}
    const int c1_rem  = tid % 36;
    const int c1_half = c1_rem / 18;         // 0..1
    const int c1_yy   = c1_rem % 18;         // 0..17
    const int c1_x0   = c1_half * 9;
    const int p0 = 2 * c1_q, p1 = p0 + 1;
    const bool rowok = interior ||
        (unsigned)(tY * TDIM + c1_yy - 1) < (unsigned)H;

    const int cy = tid >> 4, cp = tid & 15;   // conv2 task (tid < 256)

    const int   eA = g_eidx[b * 2 + 0], eB = g_eidx[b * 2 + 1];
    const float gA = g_gate[b * 2 + 0], gB = g_gate[b * 2 + 1];

    float acc2[16];
#pragma unroll
    for (int j = 0; j < 16; j++) acc2[j] = 0.f;

    for (int it = 0; it < 4; it++) {
        const int e   = (it < 2) ? eA : eB;
        const float g = (it < 2) ? gA : gB;
        const int ch  = it & 1;

        __syncthreads(); // prior conv2 reads of hs2/w2p done (covers xs fill)
        {
            const float* W1 = ew1 + e * (HID * 27) + ch * (CHP * 27);
            for (int i = tid; i < 16 * 27; i += NTHR) {
                int p = i / 27, k = i % 27;
                w1p[i] = pack2(W1[(2 * p) * 27 + k], W1[(2 * p + 1) * 27 + k]);
            }
            const float* W2 = ew2 + e * (HID * 9) + ch * (CHP * 9);
            for (int i = tid; i < 16 * 9; i += NTHR) {
                int p = i / 9, k = i % 9;
                w2p[i] = pack2(g * W2[(2 * p) * 9 + k], g * W2[(2 * p + 1) * 9 + k]);
            }
            if (tid < CHP) b1s[tid] = eb1[e * HID + ch * CHP + tid];
        }
        __syncthreads();

        // conv1 + ReLU: 2 channel-pairs x 9-wide half-row, shared x window.
        // ic loop deliberately NOT unrolled (compile-size control).
        {
            const u64 bp0 = pack2(b1s[4 * c1_q + 0], b1s[4 * c1_q + 1]);
            const u64 bp1 = pack2(b1s[4 * c1_q + 2], b1s[4 * c1_q + 3]);
            u64 a0[9], a1[9];
#pragma unroll
            for (int j = 0; j < 9; j++) { a0[j] = bp0; a1[j] = bp1; }
#pragma unroll 1
            for (int ic = 0; ic < 3; ic++) {
#pragma unroll
                for (int ky = 0; ky < 3; ky++) {
                    const float* row = &xs[(ic * 20 + c1_yy + ky) * XW + c1_x0];
                    const u64* wq0 = &w1p[p0 * 27 + ic * 9 + ky * 3];
                    const u64* wq1 = &w1p[p1 * 27 + ic * 9 + ky * 3];
                    const u64 wa0 = wq0[0], wb0 = wq0[1], wc0 = wq0[2];
                    const u64 wa1 = wq1[0], wb1 = wq1[1], wc1 = wq1[2];
                    float r0 = row[0], r1 = row[1];
                    u64 rp0 = pack2(r0, r0), rp1 = pack2(r1, r1);
#pragma unroll
                    for (int j = 0; j < 9; j++) {
                        float r2 = row[j + 2];
                        u64 rp2 = pack2(r2, r2);
                        fma2(a0[j], rp0, wa0);
                        fma2(a0[j], rp1, wb0);
                        fma2(a0[j], rp2, wc0);
                        fma2(a1[j], rp0, wa1);
                        fma2(a1[j], rp1, wb1);
                        fma2(a1[j], rp2, wc1);
                        rp0 = rp1; rp1 = rp2;
                    }
                }
            }
            u64* h0 = &hs2[p0 * HP2 + c1_yy * 19 + c1_x0];
            u64* h1 = &hs2[p1 * HP2 + c1_yy * 19 + c1_x0];
            if (interior) {
#pragma unroll
                for (int j = 0; j < 9; j++) {
                    float lo, hi;
                    unpack2(a0[j], lo, hi);
                    h0[j] = pack2(fmaxf(lo, 0.f), fmaxf(hi, 0.f));
                    unpack2(a1[j], lo, hi);
                    h1[j] = pack2(fmaxf(lo, 0.f), fmaxf(hi, 0.f));
                }
            } else {
                // conv2 SAME padding: h == 0 outside the image
#pragma unroll
                for (int j = 0; j < 9; j++) {
                    const bool ok = rowok &&
                        (unsigned)(tX * TDIM + c1_x0 + j - 1) < (unsigned)W;
                    float lo, hi;
                    unpack2(a0[j], lo, hi);
                    h0[j] = ok ? pack2(fmaxf(lo, 0.f), fmaxf(hi, 0.f)) : 0ull;
                    unpack2(a1[j], lo, hi);
                    h1[j] = ok ? pack2(fmaxf(lo, 0.f), fmaxf(hi, 0.f)) : 0ull;
                }
            }
        }
        __syncthreads();

        // conv2: pair cp, sliding window over packed h rows; lane-split
        // partials in accP, folded into scalar acc2 once per iteration.
        if (tid < 256) {
            u64 accP[16];
#pragma unroll
            for (int j = 0; j < 16; j++) accP[j] = 0ull;
            const u64* w2row = &w2p[cp * 9];
#pragma unroll
            for (int ky = 0; ky < 3; ky++) {
                const u64* row = &hs2[cp * HP2 + (cy + ky) * 19];
                const u64 wa = w2row[ky * 3], wb = w2row[ky * 3 + 1],
                          wc = w2row[ky * 3 + 2];
                u64 rp0 = row[0], rp1 = row[1];
#pragma unroll
                for (int j = 0; j < 16; j++) {
                    u64 rp2 = row[j + 2];
                    fma2(accP[j], rp0, wa);
                    fma2(accP[j], rp1, wb);
                    fma2(accP[j], rp2, wc);
                    rp0 = rp1; rp1 = rp2;
                }
            }
#pragma unroll
            for (int j = 0; j < 16; j++) {
                float lo, hi;
                unpack2(accP[j], lo, hi);
                acc2[j] += lo + hi;
            }
        }
    }

    __syncthreads(); // all hs2 reads done -> overlay part
    float* part = (float*)hs2;
    if (tid < 256) {
        float* pp = &part[cp * PICL + cy * 17];
#pragma unroll
        for (int j = 0; j < 16; j++) pp[j] = acc2[j];
    }
    __syncthreads();

    if (tid < 256) {
        const int oy = tid >> 4, ox = tid & 15;
        float yacc = 0.f;
#pragma unroll
        for (int icl = 0; icl < 16; icl++)
            yacc += part[icl * PICL + oy * 17 + ox];
        yacc += gA * eb2[eA] + gB * eb2[eB];
        out[((size_t)b << 16) + ((tY * TDIM + oy) << 8) + (tX * TDIM + ox)] = yacc;
    }
}

// ---------------- no-op pad launch (keeps k_expert at profile slot 3) ----
__global__ void k_noop() {}

// ---------------- launch ---------------------------------------------------
extern "C" void kernel_launch(void* const* d_in, const int* in_sizes, int n_in,
                              void* d_out, int out_size) {
    const float* x          = (const float*)d_in[0];
    const float* ref        = (const float*)d_in[1];
    const float* noise      = (const float*)d_in[2];
    const float* mod_w1     = (const float*)d_in[3];
    const float* mod_b1     = (const float*)d_in[4];
    const float* mod_w2     = (const float*)d_in[5];
    const float* mod_b2     = (const float*)d_in[6];
    const float* enh_w      = (const float*)d_in[7];
    const float* enh_b      = (const float*)d_in[8];
    const float* fre_prompt = (const float*)d_in[9];
    const float* w_gate     = (const float*)d_in[10];
    const float* w_noise    = (const float*)d_in[11];
    const float* ew1        = (const float*)d_in[12];
    const float* eb1        = (const float*)d_in[13];
    const float* ew2        = (const float*)d_in[14];
    const float* eb2        = (const float*)d_in[15];
    float* out = (float*)d_out;

    k_refsum<<<B * C, 256>>>(ref);                                       // 0
    k_gate_dots<<<dim3(B, GSLICE), 512>>>(x, w_gate, w_noise, mod_w1,
                                          mod_b1, mod_w2, mod_b2, enh_w,
                                          enh_b, fre_prompt);            // 1
    k_finalize<<<1, 32>>>(noise, out, out_size);                         // 2
    k_expert<<<dim3(W / TDIM, H / TDIM, B), NTHR>>>(x, ew1, eb1,
                                                    ew2, eb2, out);      // 3
    k_noop<<<1, 32>>>();                                                 // 4
}